// round 7
// baseline (speedup 1.0000x reference)
#include <cuda_runtime.h>
#include <stdint.h>

#define VOCAB 512
#define WCHARS 24
#define WPB 8                 // warps per block == rows per group
#define NBLOCKS 592           // ~4 per SM, persistent

// Persistent blocks, one warp per row within a group of 8 rows. Double-
// buffered smem histograms (2 x 16KB); TMA bulk-copies group i while the
// block builds group i+1. Tail output (lengths) fused into block 0.
// int64 inputs arrive as int32 (jax x64 disabled).
__global__ void __launch_bounds__(WPB * 32)
fofe_kernel(const int* __restrict__ sents,
            const int* __restrict__ lengths,
            const float* __restrict__ alpha_p,
            float* __restrict__ out,
            int nrows,
            long long main_elems,
            int extra,
            int nlen)
{
    __shared__ __align__(128) float hist[2][WPB][VOCAB];   // 32 KB

    const int warp = threadIdx.x >> 5;
    const int lane = threadIdx.x & 31;
    const int ngroups = (nrows + WPB - 1) / WPB;

    // fused tail: (out, lengths) second output appended to d_out
    if (blockIdx.x == 0 && (int)threadIdx.x < extra) {
        int i = threadIdx.x;
        out[main_elems + i] = (i < nlen) ? (float)lengths[i] : 0.0f;
    }

    const float a = __ldg(alpha_p);

    int it = 0;
    for (int g = blockIdx.x; g < ngroups; g += NBLOCKS, ++it) {
        const int buf  = it & 1;
        const int row0 = g * WPB;
        const int row  = row0 + warp;
        const int rows_here = min(WPB, nrows - row0);

        // make sure the TMA that last read this buffer (2 iters ago) is done
        if (threadIdx.x == 0)
            asm volatile("cp.async.bulk.wait_group 1;" ::: "memory");
        __syncthreads();

        if (warp < rows_here) {
            float* h = hist[buf][warp];

            // input load first; zero-fill overlaps its latency
            int c = 0;
            if (lane < WCHARS)
                c = sents[(long long)row * WCHARS + lane];

            // zero the 2KB row histogram: 4 x STS.128 per lane
            float4* h4 = reinterpret_cast<float4*>(h);
            const float4 z = make_float4(0.f, 0.f, 0.f, 0.f);
            #pragma unroll
            for (int j = 0; j < 4; ++j)
                h4[j * 32 + lane] = z;

            const bool valid = (lane < WCHARS) && (c > 0) && (c < VOCAB);
            const unsigned nz = __ballot_sync(0xffffffffu, valid);
            __syncwarp();                   // zeros visible before atomics

            if (valid) {
                const int suffix = __popc(nz & (0xfffffffeu << lane));
                const float w = (suffix == 0) ? 1.0f
                                              : exp2f(log2f(a) * (float)suffix);
                atomicAdd(&h[c], w);        // shared atomic, <=24 per row
            }
        }

        __syncthreads();                    // group's histograms complete

        // elected thread launches the async bulk copy; no wait here
        if (threadIdx.x == 0) {
            asm volatile("fence.proxy.async.shared::cta;" ::: "memory");
            unsigned saddr = (unsigned)__cvta_generic_to_shared(&hist[buf][0][0]);
            float*   gdst  = out + (long long)row0 * VOCAB;
            unsigned bytes = (unsigned)rows_here * VOCAB * sizeof(float);
            asm volatile(
                "cp.async.bulk.global.shared::cta.bulk_group [%0], [%1], %2;"
                :: "l"(gdst), "r"(saddr), "r"(bytes) : "memory");
            asm volatile("cp.async.bulk.commit_group;" ::: "memory");
        }
    }

    // drain all outstanding copies before the block (and its smem) retires
    if (threadIdx.x == 0)
        asm volatile("cp.async.bulk.wait_group 0;" ::: "memory");
}

extern "C" void kernel_launch(void* const* d_in, const int* in_sizes, int n_in,
                              void* d_out, int out_size)
{
    const int*   sents   = (const int*)d_in[0];
    const int*   lengths = (const int*)d_in[1];
    const float* alpha   = (const float*)d_in[2];
    float*       out     = (float*)d_out;

    const int nrows = in_sizes[0] / WCHARS;             // B*S = 32768
    const long long main_elems = (long long)nrows * VOCAB;
    const int nlen = in_sizes[1];

    long long extra_ll = (long long)out_size - main_elems;
    if (extra_ll < 0) extra_ll = 0;
    if (extra_ll > WPB * 32) extra_ll = WPB * 32;

    fofe_kernel<<<NBLOCKS, WPB * 32>>>(sents, lengths, alpha, out,
                                       nrows, main_elems, (int)extra_ll, nlen);
}

// round 8
// speedup vs baseline: 1.0043x; 1.0043x over previous
#include <cuda_runtime.h>
#include <stdint.h>

#define VOCAB 512
#define WCHARS 24
#define WPB 8                 // warps per block == rows per group
#define NBLOCKS 592           // ~4 per SM, persistent

// Persistent blocks, one warp per row per group, double-buffered smem
// histograms drained by TMA bulk copies. Buffers are zeroed ONCE; afterwards
// each lane re-zeroes only the single bin it dirtied on that buffer's
// previous use (<=24 STS.32 per row instead of 2KB). sents LDG for the group
// is prefetched before the pipeline wait. Tail (lengths) fused into block 0.
// int64 inputs arrive as int32 (jax x64 disabled).
__global__ void __launch_bounds__(WPB * 32)
fofe_kernel(const int* __restrict__ sents,
            const int* __restrict__ lengths,
            const float* __restrict__ alpha_p,
            float* __restrict__ out,
            int nrows,
            long long main_elems,
            int extra,
            int nlen)
{
    __shared__ __align__(128) float hist[2][WPB][VOCAB];   // 32 KB

    const int warp = threadIdx.x >> 5;
    const int lane = threadIdx.x & 31;
    const int ngroups = (nrows + WPB - 1) / WPB;

    // fused tail: (out, lengths) second output appended to d_out
    if (blockIdx.x == 0 && (int)threadIdx.x < extra) {
        int i = threadIdx.x;
        out[main_elems + i] = (i < nlen) ? (float)lengths[i] : 0.0f;
    }

    // one-time zero of both buffers (8 x STS.128 per thread)
    {
        float4* b4 = reinterpret_cast<float4*>(&hist[0][0][0]);
        const float4 z = make_float4(0.f, 0.f, 0.f, 0.f);
        #pragma unroll
        for (int j = 0; j < 8; ++j)
            b4[j * (WPB * 32) + threadIdx.x] = z;
    }
    __syncthreads();

    const float a = __ldg(alpha_p);

    int c_prev[2] = { -1, -1 };       // bin this lane dirtied, per buffer

    int it = 0;
    for (int g = blockIdx.x; g < ngroups; g += NBLOCKS, ++it) {
        const int buf  = it & 1;
        const int row0 = g * WPB;
        const int row  = row0 + warp;
        const int rows_here = min(WPB, nrows - row0);

        // prefetch this group's chars before the pipeline wait
        int c = 0;
        if (warp < rows_here && lane < WCHARS)
            c = sents[(long long)row * WCHARS + lane];

        // ensure the TMA that last read this buffer (2 iters ago) is done
        if (threadIdx.x == 0)
            asm volatile("cp.async.bulk.wait_group 1;" ::: "memory");
        __syncthreads();

        float* h = hist[buf][warp];

        // re-zero only the bin this lane dirtied last time on this buffer
        if (c_prev[buf] >= 0) h[c_prev[buf]] = 0.0f;
        c_prev[buf] = -1;

        const bool valid = (warp < rows_here) && (lane < WCHARS) &&
                           (c > 0) && (c < VOCAB);
        const unsigned nz = __ballot_sync(0xffffffffu, valid);
        __syncwarp();                       // re-zeros visible before atomics

        if (valid) {
            const int suffix = __popc(nz & (0xfffffffeu << lane));
            const float w = (suffix == 0) ? 1.0f
                                          : exp2f(log2f(a) * (float)suffix);
            atomicAdd(&h[c], w);            // shared atomic, <=24 per row
            c_prev[buf] = c;
        }

        __syncthreads();                    // group's histograms complete

        // elected thread launches the async bulk copy; no wait here
        if (threadIdx.x == 0) {
            asm volatile("fence.proxy.async.shared::cta;" ::: "memory");
            unsigned saddr = (unsigned)__cvta_generic_to_shared(&hist[buf][0][0]);
            float*   gdst  = out + (long long)row0 * VOCAB;
            unsigned bytes = (unsigned)rows_here * VOCAB * sizeof(float);
            asm volatile(
                "cp.async.bulk.global.shared::cta.bulk_group [%0], [%1], %2;"
                :: "l"(gdst), "r"(saddr), "r"(bytes) : "memory");
            asm volatile("cp.async.bulk.commit_group;" ::: "memory");
        }
    }

    // drain all outstanding copies before the block (and its smem) retires
    if (threadIdx.x == 0)
        asm volatile("cp.async.bulk.wait_group 0;" ::: "memory");
}

extern "C" void kernel_launch(void* const* d_in, const int* in_sizes, int n_in,
                              void* d_out, int out_size)
{
    const int*   sents   = (const int*)d_in[0];
    const int*   lengths = (const int*)d_in[1];
    const float* alpha   = (const float*)d_in[2];
    float*       out     = (float*)d_out;

    const int nrows = in_sizes[0] / WCHARS;             // B*S = 32768
    const long long main_elems = (long long)nrows * VOCAB;
    const int nlen = in_sizes[1];

    long long extra_ll = (long long)out_size - main_elems;
    if (extra_ll < 0) extra_ll = 0;
    if (extra_ll > WPB * 32) extra_ll = WPB * 32;

    fofe_kernel<<<NBLOCKS, WPB * 32>>>(sents, lengths, alpha, out,
                                       nrows, main_elems, (int)extra_ll, nlen);
}